// round 16
// baseline (speedup 1.0000x reference)
#include <cuda_runtime.h>
#include <cuda_fp16.h>
#include <math.h>
#include <stdint.h>

#define NB 16
#define NS 2048
#define ND 1024
#define NH 128

// Split half planes produced by prep/proj
__device__ __half g_qh[(size_t)NB * NS * NH];   // pre-scaled by 128^-0.5
__device__ __half g_ql[(size_t)NB * NS * NH];
__device__ __half g_kh[(size_t)NB * NS * NH];
__device__ __half g_kl[(size_t)NB * NS * NH];
__device__ __half g_vth[(size_t)NB * NH * NS];  // V transposed: [b][h][s]
__device__ __half g_vtl[(size_t)NB * NH * NS];
__device__ __half g_wth[3 * 128 * 1024];        // W^T split: [mat][n][k]
__device__ __half g_wtl[3 * 128 * 1024];
__device__ int    g_done[NB];                   // proj CTAs completed per batch

#define PROJ_PER_BATCH 48                        // 3 mats x 16 m-tiles

// ---------------------------------------------------------------------------
// Helpers
// ---------------------------------------------------------------------------
__device__ __forceinline__ uint32_t smem_u32(const void* p) {
    uint32_t a;
    asm("{ .reg .u64 t; cvta.to.shared.u64 t, %1; cvt.u32.u64 %0, t; }"
        : "=r"(a) : "l"(p));
    return a;
}

__device__ __forceinline__ void cp16(uint32_t dst, const void* src) {
    uint64_t g;
    asm("cvta.to.global.u64 %0, %1;" : "=l"(g) : "l"(src));
    asm volatile("cp.async.ca.shared.global [%0], [%1], 16;"
                 :: "r"(dst), "l"(g) : "memory");
}

#define CP_COMMIT() asm volatile("cp.async.commit_group;" ::: "memory")
#define CP_WAIT0()  asm volatile("cp.async.wait_group 0;" ::: "memory")
#define CP_WAIT1()  asm volatile("cp.async.wait_group 1;" ::: "memory")
#define CP_WAIT2()  asm volatile("cp.async.wait_group 2;" ::: "memory")

// D += A(16x16) * B(16x8), fp16 inputs, fp32 accumulate
__device__ __forceinline__ void mma_f16(float* c,
    uint32_t a0, uint32_t a1, uint32_t a2, uint32_t a3,
    uint32_t b0, uint32_t b1)
{
    asm volatile(
        "mma.sync.aligned.m16n8k16.row.col.f32.f16.f16.f32 "
        "{%0,%1,%2,%3}, {%4,%5,%6,%7}, {%8,%9}, {%0,%1,%2,%3};"
        : "+f"(c[0]), "+f"(c[1]), "+f"(c[2]), "+f"(c[3])
        : "r"(a0), "r"(a1), "r"(a2), "r"(a3), "r"(b0), "r"(b1));
}

// fp16 3-term split of a float pair -> (hi half2, lo half2)
__device__ __forceinline__ void split_h2(float x, float y,
                                         uint32_t& hi, uint32_t& lo)
{
    __half2 h = __floats2half2_rn(x, y);
    float2 hf = __half22float2(h);
    __half2 l = __floats2half2_rn(x - hf.x, y - hf.y);
    hi = *(uint32_t*)&h;
    lo = *(uint32_t*)&l;
}

// ---------------------------------------------------------------------------
// W prep: W[1024][128] fp32 -> g_wth/g_wtl [mat][n=128][k=1024] half planes.
// Also zeroes the per-batch completion flags for this launch.
// ---------------------------------------------------------------------------
__global__ void prep_w(const float* __restrict__ Wq,
                       const float* __restrict__ Wk,
                       const float* __restrict__ Wv)
{
    __shared__ float t[32][33];
    if (blockIdx.x == 0 && blockIdx.y == 0 && blockIdx.z == 0 &&
        threadIdx.x < NB)
        g_done[threadIdx.x] = 0;

    const float* W = (blockIdx.z == 0) ? Wq : (blockIdx.z == 1) ? Wk : Wv;
    int k0 = blockIdx.x * 32;
    int n0 = blockIdx.y * 32;
    int lx = threadIdx.x & 31, ly = threadIdx.x >> 5;
#pragma unroll
    for (int i = 0; i < 32; i += 8)
        t[ly + i][lx] = W[(size_t)(k0 + ly + i) * 128 + n0 + lx];
    __syncthreads();
#pragma unroll
    for (int i = 0; i < 32; i += 8) {
        float val = t[lx][ly + i];   // W[k0+lx][n0+ly+i]
        size_t o = ((size_t)blockIdx.z * 128 + n0 + ly + i) * 1024 + k0 + lx;
        __half h = __float2half_rn(val);
        g_wth[o] = h;
        g_wtl[o] = __float2half_rn(val - __half2float(h));
    }
}

// ---------------------------------------------------------------------------
// Fused producer/consumer kernel. 128 threads, 2 CTAs/SM.
// grid 1280: chunk c = bid/80 (batch), off = bid%80.
//   off <  48: proj role — mat = off%3, m-tile = c*16 + off/3 (128 rows).
//   off >= 48: attn role — batch c, qt = 31-(off-48) (heavy first); spins on
//              g_done[c] == 48 before touching q/k/v.
// ---------------------------------------------------------------------------

// proj smem: A fp32 [128][36] | Bh [128][56]h | Bl, double buffered
#define PJ_AS 36
#define PJ_BS 56
#define PJ_A_BYTES (128 * PJ_AS * 4)
#define PJ_B_BYTES (128 * PJ_BS * 2)
#define PJ_BUF_BYTES (PJ_A_BYTES + 2 * PJ_B_BYTES)   // 47104

// attn smem (halves): K[2]{h[64][136], l} | V{h[128][72], l}
#define AT_KS 136
#define AT_VS 72
#define AT_KH(st) ((st) * 17408)
#define AT_KL(st) ((st) * 17408 + 8704)
#define AT_V  34816
#define AT_VH (AT_V)
#define AT_VL (AT_V + 9216)
#define AT_QH (AT_V)
#define AT_QL (AT_V + 8704)
#define FUSED_SMEM_BYTES 106496                      // attn layout is larger

__global__ __launch_bounds__(128, 2)
void fused_pa(const float* __restrict__ X, float* __restrict__ out)
{
    extern __shared__ float smf[];
    char* smc = (char*)smf;
    __half* smh = (__half*)smf;
    const uint32_t sbase = smem_u32(smf);
    const int tid = threadIdx.x;
    const int wid = tid >> 5;
    const int lane = tid & 31;
    const int u = lane >> 2;
    const int v = lane & 3;

    const int c   = blockIdx.x / 80;
    const int off = blockIdx.x % 80;

    if (off < PROJ_PER_BATCH) {
        // ===================== PROJ ROLE =====================
        const int mat = off % 3;
        const size_t m0 = ((size_t)c * 16 + (size_t)(off / 3)) * 128;

        auto copy_tile = [&](int kt, int buf) {
            const int k0 = kt * 32;
            const uint32_t ab  = sbase + buf * PJ_BUF_BYTES;
            const uint32_t bhb = ab + PJ_A_BYTES;
            const uint32_t blb = bhb + PJ_B_BYTES;
#pragma unroll
            for (int i = 0; i < 8; i++) {           // A: 128 rows x 8 x 16B
                int e = i * 128 + tid;
                int row = e >> 3, ch = e & 7;
                cp16(ab + (row * PJ_AS + ch * 4) * 4,
                     X + (m0 + row) * ND + k0 + ch * 4);
            }
#pragma unroll
            for (int i = 0; i < 4; i++) {           // B: 128 n x 4 x 16B / plane
                int e = i * 128 + tid;
                int row = e >> 2, ch = e & 3;
                size_t wo = ((size_t)mat * 128 + row) * 1024 + k0 + ch * 8;
                cp16(bhb + (row * PJ_BS + ch * 8) * 2, g_wth + wo);
                cp16(blb + (row * PJ_BS + ch * 8) * 2, g_wtl + wo);
            }
        };

        float acc[2][16][4];
#pragma unroll
        for (int mt = 0; mt < 2; mt++)
#pragma unroll
            for (int nt = 0; nt < 16; nt++)
#pragma unroll
                for (int j = 0; j < 4; j++) acc[mt][nt][j] = 0.f;

        copy_tile(0, 0);
        CP_COMMIT();

        for (int it = 0; it < 32; it++) {
            const int buf = it & 1;
            CP_WAIT0();
            __syncthreads();
            if (it < 31) {
                copy_tile(it + 1, buf ^ 1);
                CP_COMMIT();
            }

            const float* As = smf + buf * (PJ_BUF_BYTES / 4);
            const __half* Bh = (const __half*)(smc + buf * PJ_BUF_BYTES + PJ_A_BYTES);
            const __half* Bl = Bh + PJ_B_BYTES / 2;

#pragma unroll
            for (int ks = 0; ks < 2; ks++) {
                uint32_t ah[2][4], al[2][4];
#pragma unroll
                for (int mt = 0; mt < 2; mt++) {
                    int r = wid * 32 + mt * 16 + u;
                    const float* Ap = As + r * PJ_AS + ks * 16 + 2 * v;
                    float2 f0 = *(const float2*)Ap;
                    float2 f1 = *(const float2*)(Ap + 8 * PJ_AS);
                    float2 f2 = *(const float2*)(Ap + 8);
                    float2 f3 = *(const float2*)(Ap + 8 * PJ_AS + 8);
                    split_h2(f0.x, f0.y, ah[mt][0], al[mt][0]);
                    split_h2(f1.x, f1.y, ah[mt][1], al[mt][1]);
                    split_h2(f2.x, f2.y, ah[mt][2], al[mt][2]);
                    split_h2(f3.x, f3.y, ah[mt][3], al[mt][3]);
                }
#pragma unroll
                for (int nt = 0; nt < 16; nt++) {
                    int bn = nt * 8 + u;
                    const __half* bp = Bh + bn * PJ_BS + ks * 16 + 2 * v;
                    uint32_t bh0 = *(const uint32_t*)bp;
                    uint32_t bh1 = *(const uint32_t*)(bp + 8);
                    const __half* bq = Bl + bn * PJ_BS + ks * 16 + 2 * v;
                    uint32_t bl0 = *(const uint32_t*)bq;
                    uint32_t bl1 = *(const uint32_t*)(bq + 8);
#pragma unroll
                    for (int mt = 0; mt < 2; mt++) {
                        mma_f16(acc[mt][nt], ah[mt][0], ah[mt][1], ah[mt][2], ah[mt][3], bh0, bh1);
                        mma_f16(acc[mt][nt], ah[mt][0], ah[mt][1], ah[mt][2], ah[mt][3], bl0, bl1);
                        mma_f16(acc[mt][nt], al[mt][0], al[mt][1], al[mt][2], al[mt][3], bh0, bh1);
                    }
                }
            }
        }

        __syncthreads();

        const float qscale = 0.08838834764831845f;

        if (mat < 2) {
            __half* Oh = (mat == 0) ? g_qh : g_kh;
            __half* Ol = (mat == 0) ? g_ql : g_kl;
            const float sc = (mat == 0) ? qscale : 1.0f;
#pragma unroll
            for (int mt = 0; mt < 2; mt++) {
#pragma unroll
                for (int nt = 0; nt < 16; nt++) {
                    size_t r = m0 + wid * 32 + mt * 16 + u;
                    int cc = nt * 8 + 2 * v;
                    uint32_t h01, l01, h23, l23;
                    split_h2(acc[mt][nt][0] * sc, acc[mt][nt][1] * sc, h01, l01);
                    split_h2(acc[mt][nt][2] * sc, acc[mt][nt][3] * sc, h23, l23);
                    *(uint32_t*)&Oh[r * NH + cc] = h01;
                    *(uint32_t*)&Ol[r * NH + cc] = l01;
                    *(uint32_t*)&Oh[(r + 8) * NH + cc] = h23;
                    *(uint32_t*)&Ol[(r + 8) * NH + cc] = l23;
                }
            }
        } else {
            // V: stage transpose in smem, write [b][h][s] split planes
            __half* vsh = (__half*)smc;              // [h=128][s=128]
            __half* vsl = vsh + 128 * 128;
#pragma unroll
            for (int mt = 0; mt < 2; mt++) {
#pragma unroll
                for (int nt = 0; nt < 16; nt++) {
#pragma unroll
                    for (int j = 0; j < 4; j++) {
                        int r = wid * 32 + mt * 16 + u + (j < 2 ? 0 : 8);
                        int cc = nt * 8 + 2 * v + (j & 1);
                        float val = acc[mt][nt][j];
                        __half h = __float2half_rn(val);
                        vsh[cc * 128 + r] = h;
                        vsl[cc * 128 + r] = __float2half_rn(val - __half2float(h));
                    }
                }
            }
            __syncthreads();
            size_t bb = m0 / NS;
            int s0 = (int)(m0 % NS);
#pragma unroll
            for (int i = 0; i < 16; i++) {
                int e = i * 128 + tid;
                int hrow = e >> 4, ch = e & 15;
                size_t o = (bb * NH + hrow) * NS + s0 + ch * 8;
                *(float4*)&g_vth[o] = *(float4*)&vsh[hrow * 128 + ch * 8];
                *(float4*)&g_vtl[o] = *(float4*)&vsl[hrow * 128 + ch * 8];
            }
        }

        // signal completion for this batch
        __threadfence();
        __syncthreads();
        if (tid == 0) atomicAdd(&g_done[c], 1);
        return;
    }

    // ===================== ATTN ROLE =====================
    const int b  = c;
    const int qt = 31 - (off - PROJ_PER_BATCH);     // heavy first
    const int q0 = qt * 64;
    const int njt = qt + 1;

    // wait for this batch's projections
    if (tid == 0) {
        const int* fp = &g_done[b];
        for (;;) {
            int f;
            asm volatile("ld.acquire.gpu.s32 %0, [%1];" : "=r"(f) : "l"(fp) : "memory");
            if (f >= PROJ_PER_BATCH) break;
            __nanosleep(200);
        }
    }
    __syncthreads();

    const __half* Qhg = g_qh + ((size_t)b * NS + q0) * NH;
    const __half* Qlg = g_ql + ((size_t)b * NS + q0) * NH;
    const __half* Khg = g_kh + (size_t)b * NS * NH;
    const __half* Klg = g_kl + (size_t)b * NS * NH;
    const __half* Vhg = g_vth + (size_t)b * NH * NS;
    const __half* Vlg = g_vtl + (size_t)b * NH * NS;

    // ---- stage Q (both planes) into the V area, extract register frags ----
#pragma unroll
    for (int i = 0; i < 8; i++) {
        int e = i * 128 + tid;
        int row = e >> 4, ch = e & 15;
        cp16(sbase + (AT_QH + row * AT_KS + ch * 8) * 2, Qhg + row * NH + ch * 8);
        cp16(sbase + (AT_QL + row * AT_KS + ch * 8) * 2, Qlg + row * NH + ch * 8);
    }
    CP_COMMIT();
    CP_WAIT0();
    __syncthreads();

    uint32_t qfh[8][4], qfl[8][4];
    {
        const __half* Qs = smh + AT_QH;
        const __half* Ql = smh + AT_QL;
        int r0 = wid * 16 + u;
#pragma unroll
        for (int s = 0; s < 8; s++) {
            int k = s * 16 + 2 * v;
            qfh[s][0] = *(const uint32_t*)&Qs[r0 * AT_KS + k];
            qfh[s][1] = *(const uint32_t*)&Qs[(r0 + 8) * AT_KS + k];
            qfh[s][2] = *(const uint32_t*)&Qs[r0 * AT_KS + k + 8];
            qfh[s][3] = *(const uint32_t*)&Qs[(r0 + 8) * AT_KS + k + 8];
            qfl[s][0] = *(const uint32_t*)&Ql[r0 * AT_KS + k];
            qfl[s][1] = *(const uint32_t*)&Ql[(r0 + 8) * AT_KS + k];
            qfl[s][2] = *(const uint32_t*)&Ql[r0 * AT_KS + k + 8];
            qfl[s][3] = *(const uint32_t*)&Ql[(r0 + 8) * AT_KS + k + 8];
        }
    }

    auto copy_k = [&](int j, int st) {
        const __half* kh = Khg + (size_t)(j * 64) * NH;
        const __half* kl = Klg + (size_t)(j * 64) * NH;
#pragma unroll
        for (int i = 0; i < 8; i++) {
            int e = i * 128 + tid;
            int row = e >> 4, ch = e & 15;
            cp16(sbase + (AT_KH(st) + row * AT_KS + ch * 8) * 2, kh + row * NH + ch * 8);
            cp16(sbase + (AT_KL(st) + row * AT_KS + ch * 8) * 2, kl + row * NH + ch * 8);
        }
    };
    auto copy_v = [&](int j) {
        const __half* vh = Vhg + j * 64;
        const __half* vl = Vlg + j * 64;
#pragma unroll
        for (int i = 0; i < 8; i++) {
            int e = i * 128 + tid;
            int row = e >> 3, ch = e & 7;
            cp16(sbase + (AT_VH + row * AT_VS + ch * 8) * 2, vh + (size_t)row * NS + ch * 8);
            cp16(sbase + (AT_VL + row * AT_VS + ch * 8) * 2, vl + (size_t)row * NS + ch * 8);
        }
    };

    float oacc[16][4];
#pragma unroll
    for (int nt = 0; nt < 16; nt++)
#pragma unroll
        for (int j = 0; j < 4; j++) oacc[nt][j] = 0.f;
    float m_lo = -INFINITY, m_hi = -INFINITY;
    float l_lo = 0.f, l_hi = 0.f;

    copy_k(0, 0);
    CP_COMMIT();

    for (int jt = 0; jt < njt; jt++) {
        const int st = jt & 1;
        const bool pk = (jt + 1 < njt);

        __syncthreads();
        copy_v(jt);
        CP_COMMIT();
        if (pk) {
            copy_k(jt + 1, st ^ 1);
            CP_COMMIT();
        }
        if (pk) CP_WAIT2(); else CP_WAIT1();
        __syncthreads();

        const __half* Kh = smh + AT_KH(st);
        const __half* Kl = smh + AT_KL(st);

        // ---- S = Q K^T ----
        float sacc[8][4];
#pragma unroll
        for (int nt = 0; nt < 8; nt++)
#pragma unroll
            for (int j = 0; j < 4; j++) sacc[nt][j] = 0.f;

#pragma unroll
        for (int s = 0; s < 8; s++) {
#pragma unroll
            for (int nt = 0; nt < 8; nt++) {
                int bn = nt * 8 + u;
                const __half* kp = Kh + bn * AT_KS + s * 16 + 2 * v;
                uint32_t bh0 = *(const uint32_t*)kp;
                uint32_t bh1 = *(const uint32_t*)(kp + 8);
                const __half* kq = Kl + bn * AT_KS + s * 16 + 2 * v;
                uint32_t bl0 = *(const uint32_t*)kq;
                uint32_t bl1 = *(const uint32_t*)(kq + 8);
                mma_f16(sacc[nt], qfh[s][0], qfh[s][1], qfh[s][2], qfh[s][3], bh0, bh1);
                mma_f16(sacc[nt], qfh[s][0], qfh[s][1], qfh[s][2], qfh[s][3], bl0, bl1);
                mma_f16(sacc[nt], qfl[s][0], qfl[s][1], qfl[s][2], qfl[s][3], bh0, bh1);
            }
        }

        // ---- causal mask (diagonal tile only; scale folded into Q) ----
        if (jt == njt - 1) {
            const int row_lo = q0 + wid * 16 + u;
            const int row_hi = row_lo + 8;
#pragma unroll
            for (int nt = 0; nt < 8; nt++) {
#pragma unroll
                for (int j = 0; j < 4; j++) {
                    int col = jt * 64 + nt * 8 + 2 * v + (j & 1);
                    int row = (j < 2) ? row_lo : row_hi;
                    if (col > row) sacc[nt][j] = -INFINITY;
                }
            }
        }

        // ---- online softmax ----
        float mx_lo = -INFINITY, mx_hi = -INFINITY;
#pragma unroll
        for (int nt = 0; nt < 8; nt++) {
            mx_lo = fmaxf(mx_lo, fmaxf(sacc[nt][0], sacc[nt][1]));
            mx_hi = fmaxf(mx_hi, fmaxf(sacc[nt][2], sacc[nt][3]));
        }
        mx_lo = fmaxf(mx_lo, __shfl_xor_sync(0xffffffffu, mx_lo, 1));
        mx_lo = fmaxf(mx_lo, __shfl_xor_sync(0xffffffffu, mx_lo, 2));
        mx_hi = fmaxf(mx_hi, __shfl_xor_sync(0xffffffffu, mx_hi, 1));
        mx_hi = fmaxf(mx_hi, __shfl_xor_sync(0xffffffffu, mx_hi, 2));

        float mn_lo = fmaxf(m_lo, mx_lo);
        float mn_hi = fmaxf(m_hi, mx_hi);
        float sc_lo = __expf(m_lo - mn_lo);
        float sc_hi = __expf(m_hi - mn_hi);
        m_lo = mn_lo; m_hi = mn_hi;

        float rs_lo = 0.f, rs_hi = 0.f;
#pragma unroll
        for (int nt = 0; nt < 8; nt++) {
            sacc[nt][0] = __expf(sacc[nt][0] - mn_lo);
            sacc[nt][1] = __expf(sacc[nt][1] - mn_lo);
            sacc[nt][2] = __expf(sacc[nt][2] - mn_hi);
            sacc[nt][3] = __expf(sacc[nt][3] - mn_hi);
            rs_lo += sacc[nt][0] + sacc[nt][1];
            rs_hi += sacc[nt][2] + sacc[nt][3];
        }
        rs_lo += __shfl_xor_sync(0xffffffffu, rs_lo, 1);
        rs_lo += __shfl_xor_sync(0xffffffffu, rs_lo, 2);
        rs_hi += __shfl_xor_sync(0xffffffffu, rs_hi, 1);
        rs_hi += __shfl_xor_sync(0xffffffffu, rs_hi, 2);
        l_lo = l_lo * sc_lo + rs_lo;
        l_hi = l_hi * sc_hi + rs_hi;

#pragma unroll
        for (int nt = 0; nt < 16; nt++) {
            oacc[nt][0] *= sc_lo; oacc[nt][1] *= sc_lo;
            oacc[nt][2] *= sc_hi; oacc[nt][3] *= sc_hi;
        }

        if (pk) CP_WAIT1(); else CP_WAIT0();
        __syncthreads();

        const __half* Vh = smh + AT_VH;
        const __half* Vl = smh + AT_VL;

        // ---- O += P V : P A-fragments straight from sacc registers ----
#pragma unroll
        for (int s2 = 0; s2 < 4; s2++) {
            uint32_t ph[4], pl[4];
            split_h2(sacc[2 * s2][0],     sacc[2 * s2][1],     ph[0], pl[0]);
            split_h2(sacc[2 * s2][2],     sacc[2 * s2][3],     ph[1], pl[1]);
            split_h2(sacc[2 * s2 + 1][0], sacc[2 * s2 + 1][1], ph[2], pl[2]);
            split_h2(sacc[2 * s2 + 1][2], sacc[2 * s2 + 1][3], ph[3], pl[3]);
#pragma unroll
            for (int nt = 0; nt < 16; nt++) {
                int vn = nt * 8 + u;
                const __half* vp = Vh + vn * AT_VS + s2 * 16 + 2 * v;
                uint32_t vh0 = *(const uint32_t*)vp;
                uint32_t vh1 = *(const uint32_t*)(vp + 8);
                const __half* vq = Vl + vn * AT_VS + s2 * 16 + 2 * v;
                uint32_t vl0 = *(const uint32_t*)vq;
                uint32_t vl1 = *(const uint32_t*)(vq + 8);
                mma_f16(oacc[nt], ph[0], ph[1], ph[2], ph[3], vh0, vh1);
                mma_f16(oacc[nt], ph[0], ph[1], ph[2], ph[3], vl0, vl1);
                mma_f16(oacc[nt], pl[0], pl[1], pl[2], pl[3], vh0, vh1);
            }
        }
    }

    // ---- normalize + write ----
    float inv_lo = 1.0f / l_lo;
    float inv_hi = 1.0f / l_hi;
    float* Og = out + ((size_t)b * NS + q0) * NH;
    int r = wid * 16 + u;
#pragma unroll
    for (int nt = 0; nt < 16; nt++) {
        int cc = nt * 8 + 2 * v;
        *(float2*)&Og[r * NH + cc] =
            make_float2(oacc[nt][0] * inv_lo, oacc[nt][1] * inv_lo);
        *(float2*)&Og[(r + 8) * NH + cc] =
            make_float2(oacc[nt][2] * inv_hi, oacc[nt][3] * inv_hi);
    }
}

extern "C" void kernel_launch(void* const* d_in, const int* in_sizes, int n_in,
                              void* d_out, int out_size)
{
    const float* X  = (const float*)d_in[0];
    const float* Wq = (const float*)d_in[1];
    const float* Wk = (const float*)d_in[2];
    const float* Wv = (const float*)d_in[3];
    float* out = (float*)d_out;

    // 1) split + transpose weights; zero batch-completion flags
    dim3 wgrid(32, 4, 3);
    prep_w<<<wgrid, 256>>>(Wq, Wk, Wv);

    // 2) fused proj + attention, pipelined by batch
    cudaFuncSetAttribute(fused_pa,
        cudaFuncAttributeMaxDynamicSharedMemorySize, FUSED_SMEM_BYTES);
    fused_pa<<<NB * 80, 128, FUSED_SMEM_BYTES>>>(X, out);
}

// round 17
// speedup vs baseline: 1.2972x; 1.2972x over previous
#include <cuda_runtime.h>
#include <cuda_fp16.h>
#include <math.h>
#include <stdint.h>

#define NB 16
#define NS 2048
#define ND 1024
#define NH 128

// Split half planes produced by prep/proj
__device__ __half g_qh[(size_t)NB * NS * NH];   // pre-scaled by 128^-0.5
__device__ __half g_ql[(size_t)NB * NS * NH];
__device__ __half g_kh[(size_t)NB * NS * NH];
__device__ __half g_kl[(size_t)NB * NS * NH];
__device__ __half g_vth[(size_t)NB * NH * NS];  // V transposed: [b][h][s]
__device__ __half g_vtl[(size_t)NB * NH * NS];
__device__ __half g_wth[3 * 128 * 1024];        // W^T split: [mat][n][k]
__device__ __half g_wtl[3 * 128 * 1024];

// ---------------------------------------------------------------------------
// Helpers
// ---------------------------------------------------------------------------
__device__ __forceinline__ uint32_t smem_u32(const void* p) {
    uint32_t a;
    asm("{ .reg .u64 t; cvta.to.shared.u64 t, %1; cvt.u32.u64 %0, t; }"
        : "=r"(a) : "l"(p));
    return a;
}

__device__ __forceinline__ void cp16(uint32_t dst, const void* src) {
    uint64_t g;
    asm("cvta.to.global.u64 %0, %1;" : "=l"(g) : "l"(src));
    asm volatile("cp.async.ca.shared.global [%0], [%1], 16;"
                 :: "r"(dst), "l"(g) : "memory");
}

#define CP_COMMIT() asm volatile("cp.async.commit_group;" ::: "memory")
#define CP_WAIT0()  asm volatile("cp.async.wait_group 0;" ::: "memory")
#define CP_WAIT1()  asm volatile("cp.async.wait_group 1;" ::: "memory")
#define CP_WAIT2()  asm volatile("cp.async.wait_group 2;" ::: "memory")

// D += A(16x16) * B(16x8), fp16 inputs, fp32 accumulate
__device__ __forceinline__ void mma_f16(float* c,
    uint32_t a0, uint32_t a1, uint32_t a2, uint32_t a3,
    uint32_t b0, uint32_t b1)
{
    asm volatile(
        "mma.sync.aligned.m16n8k16.row.col.f32.f16.f16.f32 "
        "{%0,%1,%2,%3}, {%4,%5,%6,%7}, {%8,%9}, {%0,%1,%2,%3};"
        : "+f"(c[0]), "+f"(c[1]), "+f"(c[2]), "+f"(c[3])
        : "r"(a0), "r"(a1), "r"(a2), "r"(a3), "r"(b0), "r"(b1));
}

// ldmatrix x4: 4 8x8 b16 matrices; lane L supplies row (L&7) of matrix (L>>3)
__device__ __forceinline__ void ldm_x4(uint32_t& r0, uint32_t& r1,
                                       uint32_t& r2, uint32_t& r3,
                                       uint32_t addr)
{
    asm volatile("ldmatrix.sync.aligned.m8n8.x4.shared.b16 {%0,%1,%2,%3}, [%4];"
        : "=r"(r0), "=r"(r1), "=r"(r2), "=r"(r3) : "r"(addr));
}

// fp16 3-term split of a float pair -> (hi half2, lo half2)
__device__ __forceinline__ void split_h2(float x, float y,
                                         uint32_t& hi, uint32_t& lo)
{
    __half2 h = __floats2half2_rn(x, y);
    float2 hf = __half22float2(h);
    __half2 l = __floats2half2_rn(x - hf.x, y - hf.y);
    hi = *(uint32_t*)&h;
    lo = *(uint32_t*)&l;
}

// ---------------------------------------------------------------------------
// W prep: W[1024][128] fp32 -> g_wth/g_wtl [mat][n=128][k=1024] half planes
// ---------------------------------------------------------------------------
__global__ void prep_w(const float* __restrict__ Wq,
                       const float* __restrict__ Wk,
                       const float* __restrict__ Wv)
{
    __shared__ float t[32][33];
    const float* W = (blockIdx.z == 0) ? Wq : (blockIdx.z == 1) ? Wk : Wv;
    int k0 = blockIdx.x * 32;
    int n0 = blockIdx.y * 32;
    int lx = threadIdx.x & 31, ly = threadIdx.x >> 5;
#pragma unroll
    for (int i = 0; i < 32; i += 8)
        t[ly + i][lx] = W[(size_t)(k0 + ly + i) * 128 + n0 + lx];
    __syncthreads();
#pragma unroll
    for (int i = 0; i < 32; i += 8) {
        float val = t[lx][ly + i];   // W[k0+lx][n0+ly+i]
        size_t o = ((size_t)blockIdx.z * 128 + n0 + ly + i) * 1024 + k0 + lx;
        __half h = __float2half_rn(val);
        g_wth[o] = h;
        g_wtl[o] = __float2half_rn(val - __half2float(h));
    }
}

// ---------------------------------------------------------------------------
// QKV projection GEMM, fp16x3 on m16n8k16 (R12 structure + ldmatrix B loads).
// grid (3, 256): bx = matrix, by = 128-row m-tile. 256 thr, 2 CTAs/SM.
// ---------------------------------------------------------------------------
#define PJ_AS 36
#define PJ_BS 56
#define PJ_A_BYTES (128 * PJ_AS * 4)
#define PJ_B_BYTES (128 * PJ_BS * 2)
#define PJ_BUF_BYTES (PJ_A_BYTES + 2 * PJ_B_BYTES)
#define PJ_SMEM (2 * PJ_BUF_BYTES)

__global__ __launch_bounds__(256, 2)
void proj_mma(const float* __restrict__ X, float* __restrict__ dummy)
{
    extern __shared__ float smf[];
    char* smc = (char*)smf;
    const uint32_t sbase = smem_u32(smf);
    const int tid = threadIdx.x;
    const int wid = tid >> 5;
    const int lane = tid & 31;
    const int u = lane >> 2;
    const int v = lane & 3;
    const int wm = wid >> 1;
    const int wn = wid & 1;
    // ldmatrix lane constants
    const int lmi  = lane & 7;           // row within 8x8 matrix
    const int lbs  = (lane >> 4) & 1;    // nt-within-pair select (m>>1)
    const int lks  = ((lane >> 3) & 1) * 8;  // k half select (m&1)*8
    const uint32_t boff = (uint32_t)((wn * 64 + lbs * 8 + lmi) * PJ_BS + lks);

    const int mat = blockIdx.x;
    const size_t m0 = (size_t)blockIdx.y * 128;

    auto copy_tile = [&](int kt, int buf) {
        const int k0 = kt * 32;
        const uint32_t ab  = sbase + buf * PJ_BUF_BYTES;
        const uint32_t bhb = ab + PJ_A_BYTES;
        const uint32_t blb = bhb + PJ_B_BYTES;
#pragma unroll
        for (int i = 0; i < 4; i++) {
            int e = i * 256 + tid;
            int row = e >> 3, c = e & 7;
            cp16(ab + (row * PJ_AS + c * 4) * 4,
                 X + (m0 + row) * ND + k0 + c * 4);
        }
#pragma unroll
        for (int i = 0; i < 2; i++) {
            int e = i * 256 + tid;
            int row = e >> 2, c = e & 3;
            size_t wo = ((size_t)mat * 128 + row) * 1024 + k0 + c * 8;
            cp16(bhb + (row * PJ_BS + c * 8) * 2, g_wth + wo);
            cp16(blb + (row * PJ_BS + c * 8) * 2, g_wtl + wo);
        }
    };

    float acc[2][8][4];
#pragma unroll
    for (int mt = 0; mt < 2; mt++)
#pragma unroll
        for (int nt = 0; nt < 8; nt++)
#pragma unroll
            for (int j = 0; j < 4; j++) acc[mt][nt][j] = 0.f;

    copy_tile(0, 0);
    CP_COMMIT();

    for (int it = 0; it < 32; it++) {
        const int buf = it & 1;
        CP_WAIT0();
        __syncthreads();
        if (it < 31) {
            copy_tile(it + 1, buf ^ 1);
            CP_COMMIT();
        }

        const float* As = smf + buf * (PJ_BUF_BYTES / 4);
        const uint32_t bhb = sbase + buf * PJ_BUF_BYTES + PJ_A_BYTES;
        const uint32_t blb = bhb + PJ_B_BYTES;

#pragma unroll
        for (int ks = 0; ks < 2; ks++) {
            uint32_t ah[2][4], al[2][4];
#pragma unroll
            for (int mt = 0; mt < 2; mt++) {
                int r = wm * 32 + mt * 16 + u;
                const float* Ap = As + r * PJ_AS + ks * 16 + 2 * v;
                float2 f0 = *(const float2*)Ap;
                float2 f1 = *(const float2*)(Ap + 8 * PJ_AS);
                float2 f2 = *(const float2*)(Ap + 8);
                float2 f3 = *(const float2*)(Ap + 8 * PJ_AS + 8);
                split_h2(f0.x, f0.y, ah[mt][0], al[mt][0]);
                split_h2(f1.x, f1.y, ah[mt][1], al[mt][1]);
                split_h2(f2.x, f2.y, ah[mt][2], al[mt][2]);
                split_h2(f3.x, f3.y, ah[mt][3], al[mt][3]);
            }
#pragma unroll
            for (int p = 0; p < 4; p++) {
                uint32_t off = (uint32_t)(p * 16 * PJ_BS + ks * 16 + boff) * 2;
                uint32_t h0, h1, h2, h3, l0, l1, l2, l3;
                ldm_x4(h0, h1, h2, h3, bhb + off);
                ldm_x4(l0, l1, l2, l3, blb + off);
#pragma unroll
                for (int mt = 0; mt < 2; mt++) {
                    mma_f16(acc[mt][2*p],   ah[mt][0], ah[mt][1], ah[mt][2], ah[mt][3], h0, h1);
                    mma_f16(acc[mt][2*p],   ah[mt][0], ah[mt][1], ah[mt][2], ah[mt][3], l0, l1);
                    mma_f16(acc[mt][2*p],   al[mt][0], al[mt][1], al[mt][2], al[mt][3], h0, h1);
                    mma_f16(acc[mt][2*p+1], ah[mt][0], ah[mt][1], ah[mt][2], ah[mt][3], h2, h3);
                    mma_f16(acc[mt][2*p+1], ah[mt][0], ah[mt][1], ah[mt][2], ah[mt][3], l2, l3);
                    mma_f16(acc[mt][2*p+1], al[mt][0], al[mt][1], al[mt][2], al[mt][3], h2, h3);
                }
            }
        }
    }

    __syncthreads();

    const float qscale = 0.08838834764831845f;

    if (mat < 2) {
        __half* Oh = (mat == 0) ? g_qh : g_kh;
        __half* Ol = (mat == 0) ? g_ql : g_kl;
        const float sc = (mat == 0) ? qscale : 1.0f;
#pragma unroll
        for (int mt = 0; mt < 2; mt++) {
#pragma unroll
            for (int nt = 0; nt < 8; nt++) {
                size_t r = m0 + wm * 32 + mt * 16 + u;
                int c = wn * 64 + nt * 8 + 2 * v;
                uint32_t h01, l01, h23, l23;
                split_h2(acc[mt][nt][0] * sc, acc[mt][nt][1] * sc, h01, l01);
                split_h2(acc[mt][nt][2] * sc, acc[mt][nt][3] * sc, h23, l23);
                *(uint32_t*)&Oh[r * NH + c] = h01;
                *(uint32_t*)&Ol[r * NH + c] = l01;
                *(uint32_t*)&Oh[(r + 8) * NH + c] = h23;
                *(uint32_t*)&Ol[(r + 8) * NH + c] = l23;
            }
        }
    } else {
        __half* vsh = (__half*)smc;
        __half* vsl = vsh + 128 * 128;
#pragma unroll
        for (int mt = 0; mt < 2; mt++) {
#pragma unroll
            for (int nt = 0; nt < 8; nt++) {
#pragma unroll
                for (int j = 0; j < 4; j++) {
                    int r = wm * 32 + mt * 16 + u + (j < 2 ? 0 : 8);
                    int c = wn * 64 + nt * 8 + 2 * v + (j & 1);
                    float val = acc[mt][nt][j];
                    __half h = __float2half_rn(val);
                    vsh[c * 128 + r] = h;
                    vsl[c * 128 + r] = __float2half_rn(val - __half2float(h));
                }
            }
        }
        __syncthreads();
        size_t bb = m0 / NS;
        int s0 = (int)(m0 % NS);
#pragma unroll
        for (int i = 0; i < 8; i++) {
            int e = i * 256 + tid;
            int hrow = e >> 4, ch = e & 15;
            size_t o = (bb * NH + hrow) * NS + s0 + ch * 8;
            *(float4*)&g_vth[o] = *(float4*)&vsh[hrow * 128 + ch * 8];
            *(float4*)&g_vtl[o] = *(float4*)&vsl[hrow * 128 + ch * 8];
        }
    }
}

// ---------------------------------------------------------------------------
// Causal flash attention, fp16x3, 2 CTAs/SM (R12 structure + ldmatrix loads).
// CTA: 128 threads (4 warps), BQ=64 (warp owns 16 q-rows), BKV=64, H=128.
// grid (32, 16): qt = 31 - bx (heavy first), b = by.
// ---------------------------------------------------------------------------
#define AT_KS 136
#define AT_VS 72
#define AT_KH(st) ((st) * 17408)
#define AT_KL(st) ((st) * 17408 + 8704)
#define AT_V  34816
#define AT_VH (AT_V)
#define AT_VL (AT_V + 9216)
#define AT_QH (AT_V)
#define AT_QL (AT_V + 8704)
#define AT_SMEM_BYTES ((34816 + 18432) * 2)      // 106496

__global__ __launch_bounds__(128, 2)
void attn_mma(float* __restrict__ out)
{
    extern __shared__ __half smh[];
    const uint32_t sbase = smem_u32(smh);
    const int tid = threadIdx.x;
    const int wid = tid >> 5;
    const int lane = tid & 31;
    const int u = lane >> 2;
    const int v = lane & 3;
    // ldmatrix lane constants
    const int lmi = lane & 7;
    const int lbs = (lane >> 4) & 1;
    const int lks = ((lane >> 3) & 1) * 8;
    const uint32_t koff = (uint32_t)((lbs * 8 + lmi) * AT_KS + lks);
    const uint32_t voff = (uint32_t)((lbs * 8 + lmi) * AT_VS + lks);

    const int b  = blockIdx.y;
    const int qt = (int)(gridDim.x - 1) - (int)blockIdx.x;  // heavy first
    const int q0 = qt * 64;
    const int njt = qt + 1;

    const __half* Qhg = g_qh + ((size_t)b * NS + q0) * NH;
    const __half* Qlg = g_ql + ((size_t)b * NS + q0) * NH;
    const __half* Khg = g_kh + (size_t)b * NS * NH;
    const __half* Klg = g_kl + (size_t)b * NS * NH;
    const __half* Vhg = g_vth + (size_t)b * NH * NS;
    const __half* Vlg = g_vtl + (size_t)b * NH * NS;

    // ---- stage Q (both planes) into the V area, extract register frags ----
#pragma unroll
    for (int i = 0; i < 8; i++) {
        int e = i * 128 + tid;
        int row = e >> 4, ch = e & 15;
        cp16(sbase + (AT_QH + row * AT_KS + ch * 8) * 2, Qhg + row * NH + ch * 8);
        cp16(sbase + (AT_QL + row * AT_KS + ch * 8) * 2, Qlg + row * NH + ch * 8);
    }
    CP_COMMIT();
    CP_WAIT0();
    __syncthreads();

    uint32_t qfh[8][4], qfl[8][4];
    {
        const __half* Qs = smh + AT_QH;
        const __half* Ql = smh + AT_QL;
        int r0 = wid * 16 + u;
#pragma unroll
        for (int s = 0; s < 8; s++) {
            int k = s * 16 + 2 * v;
            qfh[s][0] = *(const uint32_t*)&Qs[r0 * AT_KS + k];
            qfh[s][1] = *(const uint32_t*)&Qs[(r0 + 8) * AT_KS + k];
            qfh[s][2] = *(const uint32_t*)&Qs[r0 * AT_KS + k + 8];
            qfh[s][3] = *(const uint32_t*)&Qs[(r0 + 8) * AT_KS + k + 8];
            qfl[s][0] = *(const uint32_t*)&Ql[r0 * AT_KS + k];
            qfl[s][1] = *(const uint32_t*)&Ql[(r0 + 8) * AT_KS + k];
            qfl[s][2] = *(const uint32_t*)&Ql[r0 * AT_KS + k + 8];
            qfl[s][3] = *(const uint32_t*)&Ql[(r0 + 8) * AT_KS + k + 8];
        }
    }

    auto copy_k = [&](int j, int st) {
        const __half* kh = Khg + (size_t)(j * 64) * NH;
        const __half* kl = Klg + (size_t)(j * 64) * NH;
#pragma unroll
        for (int i = 0; i < 8; i++) {
            int e = i * 128 + tid;
            int row = e >> 4, ch = e & 15;
            cp16(sbase + (AT_KH(st) + row * AT_KS + ch * 8) * 2, kh + row * NH + ch * 8);
            cp16(sbase + (AT_KL(st) + row * AT_KS + ch * 8) * 2, kl + row * NH + ch * 8);
        }
    };
    auto copy_v = [&](int j) {
        const __half* vh = Vhg + j * 64;
        const __half* vl = Vlg + j * 64;
#pragma unroll
        for (int i = 0; i < 8; i++) {
            int e = i * 128 + tid;
            int row = e >> 3, ch = e & 7;
            cp16(sbase + (AT_VH + row * AT_VS + ch * 8) * 2, vh + (size_t)row * NS + ch * 8);
            cp16(sbase + (AT_VL + row * AT_VS + ch * 8) * 2, vl + (size_t)row * NS + ch * 8);
        }
    };

    float oacc[16][4];
#pragma unroll
    for (int nt = 0; nt < 16; nt++)
#pragma unroll
        for (int j = 0; j < 4; j++) oacc[nt][j] = 0.f;
    float m_lo = -INFINITY, m_hi = -INFINITY;
    float l_lo = 0.f, l_hi = 0.f;

    copy_k(0, 0);
    CP_COMMIT();

    for (int jt = 0; jt < njt; jt++) {
        const int st = jt & 1;
        const bool pk = (jt + 1 < njt);

        __syncthreads();
        copy_v(jt);
        CP_COMMIT();
        if (pk) {
            copy_k(jt + 1, st ^ 1);
            CP_COMMIT();
        }
        if (pk) CP_WAIT2(); else CP_WAIT1();
        __syncthreads();

        const uint32_t kb_h = sbase + (AT_KH(st) + koff) * 2;
        const uint32_t kb_l = sbase + (AT_KL(st) + koff) * 2;

        // ---- S = Q K^T ----
        float sacc[8][4];
#pragma unroll
        for (int nt = 0; nt < 8; nt++)
#pragma unroll
            for (int j = 0; j < 4; j++) sacc[nt][j] = 0.f;

#pragma unroll
        for (int s = 0; s < 8; s++) {
#pragma unroll
            for (int p = 0; p < 4; p++) {
                uint32_t off = (uint32_t)(p * 16 * AT_KS + s * 16) * 2;
                uint32_t h0, h1, h2, h3, l0, l1, l2, l3;
                ldm_x4(h0, h1, h2, h3, kb_h + off);
                ldm_x4(l0, l1, l2, l3, kb_l + off);
                mma_f16(sacc[2*p],   qfh[s][0], qfh[s][1], qfh[s][2], qfh[s][3], h0, h1);
                mma_f16(sacc[2*p],   qfh[s][0], qfh[s][1], qfh[s][2], qfh[s][3], l0, l1);
                mma_f16(sacc[2*p],   qfl[s][0], qfl[s][1], qfl[s][2], qfl[s][3], h0, h1);
                mma_f16(sacc[2*p+1], qfh[s][0], qfh[s][1], qfh[s][2], qfh[s][3], h2, h3);
                mma_f16(sacc[2*p+1], qfh[s][0], qfh[s][1], qfh[s][2], qfh[s][3], l2, l3);
                mma_f16(sacc[2*p+1], qfl[s][0], qfl[s][1], qfl[s][2], qfl[s][3], h2, h3);
            }
        }

        // ---- causal mask (diagonal tile only; scale folded into Q) ----
        if (jt == njt - 1) {
            const int row_lo = q0 + wid * 16 + u;
            const int row_hi = row_lo + 8;
#pragma unroll
            for (int nt = 0; nt < 8; nt++) {
#pragma unroll
                for (int j = 0; j < 4; j++) {
                    int col = jt * 64 + nt * 8 + 2 * v + (j & 1);
                    int row = (j < 2) ? row_lo : row_hi;
                    if (col > row) sacc[nt][j] = -INFINITY;
                }
            }
        }

        // ---- online softmax ----
        float mx_lo = -INFINITY, mx_hi = -INFINITY;
#pragma unroll
        for (int nt = 0; nt < 8; nt++) {
            mx_lo = fmaxf(mx_lo, fmaxf(sacc[nt][0], sacc[nt][1]));
            mx_hi = fmaxf(mx_hi, fmaxf(sacc[nt][2], sacc[nt][3]));
        }
        mx_lo = fmaxf(mx_lo, __shfl_xor_sync(0xffffffffu, mx_lo, 1));
        mx_lo = fmaxf(mx_lo, __shfl_xor_sync(0xffffffffu, mx_lo, 2));
        mx_hi = fmaxf(mx_hi, __shfl_xor_sync(0xffffffffu, mx_hi, 1));
        mx_hi = fmaxf(mx_hi, __shfl_xor_sync(0xffffffffu, mx_hi, 2));

        float mn_lo = fmaxf(m_lo, mx_lo);
        float mn_hi = fmaxf(m_hi, mx_hi);
        float sc_lo = __expf(m_lo - mn_lo);
        float sc_hi = __expf(m_hi - mn_hi);
        m_lo = mn_lo; m_hi = mn_hi;

        float rs_lo = 0.f, rs_hi = 0.f;
#pragma unroll
        for (int nt = 0; nt < 8; nt++) {
            sacc[nt][0] = __expf(sacc[nt][0] - mn_lo);
            sacc[nt][1] = __expf(sacc[nt][1] - mn_lo);
            sacc[nt][2] = __expf(sacc[nt][2] - mn_hi);
            sacc[nt][3] = __expf(sacc[nt][3] - mn_hi);
            rs_lo += sacc[nt][0] + sacc[nt][1];
            rs_hi += sacc[nt][2] + sacc[nt][3];
        }
        rs_lo += __shfl_xor_sync(0xffffffffu, rs_lo, 1);
        rs_lo += __shfl_xor_sync(0xffffffffu, rs_lo, 2);
        rs_hi += __shfl_xor_sync(0xffffffffu, rs_hi, 1);
        rs_hi += __shfl_xor_sync(0xffffffffu, rs_hi, 2);
        l_lo = l_lo * sc_lo + rs_lo;
        l_hi = l_hi * sc_hi + rs_hi;

#pragma unroll
        for (int nt = 0; nt < 16; nt++) {
            oacc[nt][0] *= sc_lo; oacc[nt][1] *= sc_lo;
            oacc[nt][2] *= sc_hi; oacc[nt][3] *= sc_hi;
        }

        if (pk) CP_WAIT1(); else CP_WAIT0();
        __syncthreads();

        const uint32_t vb_h = sbase + (AT_VH + voff) * 2;
        const uint32_t vb_l = sbase + (AT_VL + voff) * 2;

        // ---- O += P V : P A-fragments straight from sacc registers ----
#pragma unroll
        for (int s2 = 0; s2 < 4; s2++) {
            uint32_t ph[4], pl[4];
            split_h2(sacc[2 * s2][0],     sacc[2 * s2][1],     ph[0], pl[0]);
            split_h2(sacc[2 * s2][2],     sacc[2 * s2][3],     ph[1], pl[1]);
            split_h2(sacc[2 * s2 + 1][0], sacc[2 * s2 + 1][1], ph[2], pl[2]);
            split_h2(sacc[2 * s2 + 1][2], sacc[2 * s2 + 1][3], ph[3], pl[3]);
#pragma unroll
            for (int p = 0; p < 8; p++) {
                uint32_t off = (uint32_t)(p * 16 * AT_VS + s2 * 16) * 2;
                uint32_t h0, h1, h2, h3, l0, l1, l2, l3;
                ldm_x4(h0, h1, h2, h3, vb_h + off);
                ldm_x4(l0, l1, l2, l3, vb_l + off);
                mma_f16(oacc[2*p],   ph[0], ph[1], ph[2], ph[3], h0, h1);
                mma_f16(oacc[2*p],   ph[0], ph[1], ph[2], ph[3], l0, l1);
                mma_f16(oacc[2*p],   pl[0], pl[1], pl[2], pl[3], h0, h1);
                mma_f16(oacc[2*p+1], ph[0], ph[1], ph[2], ph[3], h2, h3);
                mma_f16(oacc[2*p+1], ph[0], ph[1], ph[2], ph[3], l2, l3);
                mma_f16(oacc[2*p+1], pl[0], pl[1], pl[2], pl[3], h2, h3);
            }
        }
    }

    // ---- normalize + write ----
    float inv_lo = 1.0f / l_lo;
    float inv_hi = 1.0f / l_hi;
    float* Og = out + ((size_t)b * NS + q0) * NH;
    int r = wid * 16 + u;
#pragma unroll
    for (int nt = 0; nt < 16; nt++) {
        int c = nt * 8 + 2 * v;
        *(float2*)&Og[r * NH + c] =
            make_float2(oacc[nt][0] * inv_lo, oacc[nt][1] * inv_lo);
        *(float2*)&Og[(r + 8) * NH + c] =
            make_float2(oacc[nt][2] * inv_hi, oacc[nt][3] * inv_hi);
    }
}

extern "C" void kernel_launch(void* const* d_in, const int* in_sizes, int n_in,
                              void* d_out, int out_size)
{
    const float* X  = (const float*)d_in[0];
    const float* Wq = (const float*)d_in[1];
    const float* Wk = (const float*)d_in[2];
    const float* Wv = (const float*)d_in[3];
    float* out = (float*)d_out;

    // 1) split + transpose weights
    dim3 wgrid(32, 4, 3);
    prep_w<<<wgrid, 256>>>(Wq, Wk, Wv);

    // 2) QKV projection (fp16x3)
    cudaFuncSetAttribute(proj_mma,
        cudaFuncAttributeMaxDynamicSharedMemorySize, PJ_SMEM);
    dim3 pgrid(3, (NB * NS) / 128);
    proj_mma<<<pgrid, 256, PJ_SMEM>>>(X, nullptr);

    // 3) attention (fp16x3), 2 CTAs/SM
    cudaFuncSetAttribute(attn_mma,
        cudaFuncAttributeMaxDynamicSharedMemorySize, AT_SMEM_BYTES);
    dim3 agrid(NS / 64, NB);
    attn_mma<<<agrid, 128, AT_SMEM_BYTES>>>(out);
}